// round 3
// baseline (speedup 1.0000x reference)
#include <cuda_runtime.h>
#include <math.h>

// Problem shape (fixed by the reference): B=64, T=2048, D=U=256.
#define B_     64
#define T_     2048
#define D_     256
#define NCHUNK 8          // T-chunks per batch row
#define TCHUNK (T_ / NCHUNK)   // 256 t-rows per block
#define TSUB   32         // rows per SMEM subtile

// Scratch (allocation-free rule -> __device__ globals)
__device__ float g_w[D_];                       // w = W @ v
__device__ float g_pm[B_ * NCHUNK];             // per-chunk running max
__device__ float g_pz[B_ * NCHUNK];             // per-chunk running sum(exp)
__device__ float g_pacc[B_ * NCHUNK * D_];      // per-chunk weighted accumulators

// ---------------------------------------------------------------------------
// Kernel 1: w[d] = sum_u W[d,u] * v[u].  Warp-per-row, float4 loads.
// ---------------------------------------------------------------------------
__global__ void k_wv(const float* __restrict__ W, const float* __restrict__ v) {
    const int lane = threadIdx.x & 31;
    const int warp = threadIdx.x >> 5;
    const float4* v4 = (const float4*)v;
    const float4 va = v4[lane];
    const float4 vb = v4[32 + lane];
    for (int r = warp; r < D_; r += 8) {
        const float4* row = (const float4*)(W + r * D_);
        float4 xa = row[lane];
        float4 xb = row[32 + lane];
        float s = xa.x * va.x + xa.y * va.y + xa.z * va.z + xa.w * va.w
                + xb.x * vb.x + xb.y * vb.y + xb.z * vb.z + xb.w * vb.w;
        #pragma unroll
        for (int o = 16; o > 0; o >>= 1) s += __shfl_xor_sync(0xffffffffu, s, o);
        if (lane == 0) g_w[r] = s;
    }
}

// ---------------------------------------------------------------------------
// Kernel 2: fused scores + online softmax + weighted accumulation.
// One block per (b, chunk). x is read from DRAM exactly once.
// ---------------------------------------------------------------------------
__global__ __launch_bounds__(256) void k_chunk(const float* __restrict__ x) {
    __shared__ float sx[TSUB * D_];   // 32 KB tile
    __shared__ float s_vals[TSUB];    // per-row scores
    __shared__ float p_vals[TSUB];    // per-row exp(score - m)

    const int tid  = threadIdx.x;
    const int lane = tid & 31;
    const int warp = tid >> 5;
    const int b = blockIdx.y;
    const int c = blockIdx.x;

    // w fragments held in registers (same two float4 per lane for every row)
    const float4* w4 = (const float4*)g_w;
    const float4 wa = w4[lane];
    const float4 wb = w4[32 + lane];

    float m = -INFINITY;   // running max   (identical across threads)
    float Z = 0.0f;        // running sum-exp (identical across threads)
    float acc = 0.0f;      // thread tid owns output dim d = tid

    const size_t base = ((size_t)b * T_ + (size_t)c * TCHUNK) * D_;

    for (int s = 0; s < TCHUNK / TSUB; s++) {
        // ---- load 32x256 tile, coalesced float4 ----
        const float4* gx = (const float4*)(x + base + (size_t)s * TSUB * D_);
        float4* s4 = (float4*)sx;
        #pragma unroll
        for (int i = 0; i < 8; i++) s4[i * 256 + tid] = gx[i * 256 + tid];
        __syncthreads();

        // ---- warp-per-row dot: scores for 32 rows ----
        #pragma unroll
        for (int j = 0; j < 4; j++) {
            const int row = warp * 4 + j;
            const float4* r4 = (const float4*)(sx + row * D_);
            float4 xa = r4[lane];
            float4 xb = r4[32 + lane];
            float sc = xa.x * wa.x + xa.y * wa.y + xa.z * wa.z + xa.w * wa.w
                     + xb.x * wb.x + xb.y * wb.y + xb.z * wb.z + xb.w * wb.w;
            #pragma unroll
            for (int o = 16; o > 0; o >>= 1) sc += __shfl_xor_sync(0xffffffffu, sc, o);
            if (lane == 0) s_vals[row] = sc;
        }
        __syncthreads();

        // ---- online softmax update (all threads compute identical m/scale) ----
        float msub = -INFINITY;
        #pragma unroll
        for (int t = 0; t < TSUB; t++) msub = fmaxf(msub, s_vals[t]);
        const float mnew  = fmaxf(m, msub);
        const float scale = __expf(m - mnew);   // 0 on first subtile (m = -inf)

        if (tid < TSUB) p_vals[tid] = __expf(s_vals[tid] - mnew);
        __syncthreads();

        acc *= scale;
        Z   *= scale;
        float zs = 0.0f;
        #pragma unroll
        for (int t = 0; t < TSUB; t++) {
            const float p = p_vals[t];                 // broadcast LDS
            acc = fmaf(p, sx[t * D_ + tid], acc);      // conflict-free LDS
            zs += p;
        }
        Z += zs;
        m  = mnew;
        __syncthreads();   // protect sx / s_vals before next subtile
    }

    const int idx = b * NCHUNK + c;
    g_pacc[(size_t)idx * D_ + tid] = acc;
    if (tid == 0) { g_pm[idx] = m; g_pz[idx] = Z; }
}

// ---------------------------------------------------------------------------
// Kernel 3: merge the 8 chunk partials per batch row, write out[b, d].
// ---------------------------------------------------------------------------
__global__ void k_merge(float* __restrict__ out) {
    const int b = blockIdx.x;
    const int tid = threadIdx.x;

    float M = -INFINITY;
    #pragma unroll
    for (int c = 0; c < NCHUNK; c++) M = fmaxf(M, g_pm[b * NCHUNK + c]);

    float Z = 0.0f, o = 0.0f;
    #pragma unroll
    for (int c = 0; c < NCHUNK; c++) {
        const float e = __expf(g_pm[b * NCHUNK + c] - M);
        Z += e * g_pz[b * NCHUNK + c];
        o += e * g_pacc[(size_t)(b * NCHUNK + c) * D_ + tid];
    }
    out[b * D_ + tid] = o / Z;
}

// ---------------------------------------------------------------------------
// Inputs (metadata order): 0:x 1:g 2:W 3:Wg 4:b 5:v
// g, Wg, b are provably dead (softmax shift invariance).
// ---------------------------------------------------------------------------
extern "C" void kernel_launch(void* const* d_in, const int* in_sizes, int n_in,
                              void* d_out, int out_size) {
    const float* x = (const float*)d_in[0];
    const float* W = (const float*)d_in[2];
    const float* v = (const float*)d_in[5];
    float* out = (float*)d_out;

    k_wv<<<1, 256>>>(W, v);
    k_chunk<<<dim3(NCHUNK, B_), 256>>>(x);
    k_merge<<<B_, 256>>>(out);
}

// round 4
// speedup vs baseline: 1.6648x; 1.6648x over previous
#include <cuda_runtime.h>
#include <math.h>
#include <stdint.h>

// Problem shape (fixed by the reference): B=64, T=2048, D=U=256.
#define B_     64
#define T_     2048
#define D_     256
#define NCHUNK 4                 // T-chunks per batch row
#define TCHUNK (T_ / NCHUNK)     // 512 t-rows per block
#define TSUB   32                // rows per SMEM subtile
#define NSUB   (TCHUNK / TSUB)   // 16 subtiles

// Scratch (allocation-free rule -> __device__ globals)
__device__ float g_w[D_];                       // w = W @ v
__device__ float g_pm[B_ * NCHUNK];             // per-chunk running max
__device__ float g_pz[B_ * NCHUNK];             // per-chunk running sum(exp)
__device__ float g_pacc[B_ * NCHUNK * D_];      // per-chunk weighted accumulators

// ---------------------------------------------------------------------------
// cp.async helpers (LDGSTS on sm_103a)
// ---------------------------------------------------------------------------
__device__ __forceinline__ void cp_async16(uint32_t smem_addr, const void* gptr) {
    asm volatile("cp.async.cg.shared.global [%0], [%1], 16;\n"
                 :: "r"(smem_addr), "l"(gptr) : "memory");
}
__device__ __forceinline__ void cp_commit() {
    asm volatile("cp.async.commit_group;\n" ::: "memory");
}
__device__ __forceinline__ void cp_wait_all() {
    asm volatile("cp.async.wait_group 0;\n" ::: "memory");
}

// ---------------------------------------------------------------------------
// Kernel 1: w[d] = sum_u W[d,u] * v[u].  64 blocks x 128 threads, warp-per-row.
// ---------------------------------------------------------------------------
__global__ void k_wv(const float* __restrict__ W, const float* __restrict__ v) {
    const int lane = threadIdx.x & 31;
    const int warp = threadIdx.x >> 5;
    const int r = blockIdx.x * 4 + warp;           // 64*4 = 256 rows

    const float4* v4 = (const float4*)v;
    const float4 va = v4[lane];
    const float4 vb = v4[32 + lane];

    const float4* row = (const float4*)(W + r * D_);
    const float4 xa = row[lane];
    const float4 xb = row[32 + lane];
    float s = xa.x * va.x + xa.y * va.y + xa.z * va.z + xa.w * va.w
            + xb.x * vb.x + xb.y * vb.y + xb.z * vb.z + xb.w * vb.w;
    #pragma unroll
    for (int o = 16; o > 0; o >>= 1) s += __shfl_xor_sync(0xffffffffu, s, o);
    if (lane == 0) g_w[r] = s;
}

// ---------------------------------------------------------------------------
// Kernel 2: fused scores + online softmax + weighted accumulation.
// One block per (b, chunk). x is read from DRAM exactly once, via a
// double-buffered cp.async pipeline (tile s+1 loads under tile s compute).
// ---------------------------------------------------------------------------
__global__ __launch_bounds__(256) void k_chunk(const float* __restrict__ x) {
    __shared__ float sx[2][TSUB * D_];   // 2 x 32 KB tiles
    __shared__ float s_vals[TSUB];       // per-row scores
    __shared__ float p_vals[TSUB];       // per-row exp(score - m)

    const int tid  = threadIdx.x;
    const int lane = tid & 31;
    const int warp = tid >> 5;
    const int b = blockIdx.y;
    const int c = blockIdx.x;

    // w fragments held in registers (same two float4 per lane for every row)
    const float4* w4 = (const float4*)g_w;
    const float4 wa = w4[lane];
    const float4 wb = w4[32 + lane];

    float m = -INFINITY;   // running max      (identical across threads)
    float Z = 0.0f;        // running sum-exp  (identical across threads)
    float acc = 0.0f;      // thread tid owns output dim d = tid

    const size_t base = ((size_t)b * T_ + (size_t)c * TCHUNK) * D_;

    const uint32_t sb0 = (uint32_t)__cvta_generic_to_shared(&sx[0][0]);
    const uint32_t sb1 = (uint32_t)__cvta_generic_to_shared(&sx[1][0]);

    // issue tile s into buffer buf (8 x 16B per thread = 32 KB total)
    auto issue_tile = [&](int s, int buf) {
        const float4* gx = (const float4*)(x + base + (size_t)s * TSUB * D_);
        const uint32_t sb = buf ? sb1 : sb0;
        #pragma unroll
        for (int i = 0; i < 8; i++)
            cp_async16(sb + (uint32_t)(i * 256 + tid) * 16u, gx + i * 256 + tid);
        cp_commit();
    };

    issue_tile(0, 0);

    for (int s = 0; s < NSUB; s++) {
        const int cur = s & 1;

        cp_wait_all();          // tile s landed (only one group ever in flight)
        __syncthreads();        // make it visible block-wide; also guarantees
                                // everyone is done reading buffer cur^1

        if (s + 1 < NSUB) issue_tile(s + 1, cur ^ 1);   // overlaps compute below

        // ---- warp-per-row dot: scores for 32 rows ----
        const float* tile = &sx[cur][0];
        #pragma unroll
        for (int j = 0; j < 4; j++) {
            const int row = warp * 4 + j;
            const float4* r4 = (const float4*)(tile + row * D_);
            float4 xa = r4[lane];
            float4 xb = r4[32 + lane];
            float sc = xa.x * wa.x + xa.y * wa.y + xa.z * wa.z + xa.w * wa.w
                     + xb.x * wb.x + xb.y * wb.y + xb.z * wb.z + xb.w * wb.w;
            #pragma unroll
            for (int o = 16; o > 0; o >>= 1) sc += __shfl_xor_sync(0xffffffffu, sc, o);
            if (lane == 0) s_vals[row] = sc;
        }
        __syncthreads();

        // ---- online softmax update (all threads compute identical m/scale) ----
        float msub = -INFINITY;
        #pragma unroll
        for (int t = 0; t < TSUB; t++) msub = fmaxf(msub, s_vals[t]);
        const float mnew  = fmaxf(m, msub);
        const float scale = __expf(m - mnew);   // 0 on first subtile (m = -inf)

        if (tid < TSUB) p_vals[tid] = __expf(s_vals[tid] - mnew);
        __syncthreads();

        acc *= scale;
        Z   *= scale;
        float zs = 0.0f;
        #pragma unroll
        for (int t = 0; t < TSUB; t++) {
            const float p = p_vals[t];                    // broadcast LDS
            acc = fmaf(p, tile[t * D_ + tid], acc);       // conflict-free LDS
            zs += p;
        }
        Z += zs;
        m  = mnew;
        // no trailing sync: next iteration's post-wait __syncthreads covers
        // the buffer swap, and s_vals/p_vals rewrites happen after later syncs.
    }

    const int idx = b * NCHUNK + c;
    g_pacc[(size_t)idx * D_ + tid] = acc;
    if (tid == 0) { g_pm[idx] = m; g_pz[idx] = Z; }
}

// ---------------------------------------------------------------------------
// Kernel 3: merge the NCHUNK chunk partials per batch row, write out[b, d].
// ---------------------------------------------------------------------------
__global__ void k_merge(float* __restrict__ out) {
    const int b = blockIdx.x;
    const int tid = threadIdx.x;

    float M = -INFINITY;
    #pragma unroll
    for (int c = 0; c < NCHUNK; c++) M = fmaxf(M, g_pm[b * NCHUNK + c]);

    float Z = 0.0f, o = 0.0f;
    #pragma unroll
    for (int c = 0; c < NCHUNK; c++) {
        const float e = __expf(g_pm[b * NCHUNK + c] - M);
        Z += e * g_pz[b * NCHUNK + c];
        o += e * g_pacc[(size_t)(b * NCHUNK + c) * D_ + tid];
    }
    out[b * D_ + tid] = o / Z;
}

// ---------------------------------------------------------------------------
// Inputs (metadata order): 0:x 1:g 2:W 3:Wg 4:b 5:v
// g, Wg, b are provably dead (softmax shift invariance).
// ---------------------------------------------------------------------------
extern "C" void kernel_launch(void* const* d_in, const int* in_sizes, int n_in,
                              void* d_out, int out_size) {
    const float* x = (const float*)d_in[0];
    const float* W = (const float*)d_in[2];
    const float* v = (const float*)d_in[5];
    float* out = (float*)d_out;

    k_wv<<<64, 128>>>(W, v);
    k_chunk<<<dim3(NCHUNK, B_), 256>>>(x);
    k_merge<<<B_, 256>>>(out);
}